// round 1
// baseline (speedup 1.0000x reference)
#include <cuda_runtime.h>

#define ROWS_PER_BLOCK 32
#define THREADS 256          // 8 threads per 64-pt FFT
#define PAD 65               // row stride in float2 to stagger smem banks

__device__ __forceinline__ float2 cadd(float2 a, float2 b){ return make_float2(a.x+b.x, a.y+b.y); }
__device__ __forceinline__ float2 csub(float2 a, float2 b){ return make_float2(a.x-b.x, a.y-b.y); }
__device__ __forceinline__ float2 cmul(float2 a, float2 b){
    return make_float2(fmaf(a.x, b.x, -a.y*b.y), fmaf(a.x, b.y, a.y*b.x));
}
// multiply by -i
__device__ __forceinline__ float2 mul_mi(float2 a){ return make_float2(a.y, -a.x); }

// 8-point FFT, natural-order in, natural-order out (DIF + bit-reversal fixup).
__device__ __forceinline__ void fft8(float2 v[8]) {
    const float C = 0.70710678118654752440f;
    float2 a0=v[0],a1=v[1],a2=v[2],a3=v[3],a4=v[4],a5=v[5],a6=v[6],a7=v[7];
    // stage 1 (span 4), twiddles W8^j on the difference path
    float2 b0=cadd(a0,a4), b4=csub(a0,a4);
    float2 b1=cadd(a1,a5), t5=csub(a1,a5);
    float2 b2=cadd(a2,a6), t6=csub(a2,a6);
    float2 b3=cadd(a3,a7), t7=csub(a3,a7);
    float2 b5 = make_float2(C*(t5.x+t5.y), C*(t5.y-t5.x));   // * (C,-C)  = W8^1
    float2 b6 = mul_mi(t6);                                   // * -i      = W8^2
    float2 b7 = make_float2(C*(t7.y-t7.x), -C*(t7.x+t7.y));  // * (-C,-C) = W8^3
    // stage 2 (span 2), twiddles 1, -i
    float2 c0=cadd(b0,b2), c2=csub(b0,b2);
    float2 c1=cadd(b1,b3), c3=mul_mi(csub(b1,b3));
    float2 c4=cadd(b4,b6), c6=csub(b4,b6);
    float2 c5=cadd(b5,b7), c7=mul_mi(csub(b5,b7));
    // stage 3 (span 1)
    float2 d0=cadd(c0,c1), d1=csub(c0,c1);
    float2 d2=cadd(c2,c3), d3=csub(c2,c3);
    float2 d4=cadd(c4,c5), d5=csub(c4,c5);
    float2 d6=cadd(c6,c7), d7=csub(c6,c7);
    // bit-reversed placement -> natural order output
    v[0]=d0; v[4]=d1; v[2]=d2; v[6]=d3; v[1]=d4; v[5]=d5; v[3]=d6; v[7]=d7;
}

// One block = 32 independent FFT-64 rows. Radix-8 x radix-8 with smem transpose.
// x[n], n = n2 + 8*n1 ; X[k], k = k1 + 8*k2
// inner FFT8 over n1 (thread owns n2 = lane), twiddle W64^{n2*k1},
// smem transpose, outer FFT8 over n2, fftshift folded into final write index.
__global__ void __launch_bounds__(THREADS)
fft64_kernel(const float2* __restrict__ in, float2* __restrict__ out) {
    __shared__ float2 sm[ROWS_PER_BLOCK * PAD];
    const int tid = threadIdx.x;
    const long long rowbase = (long long)blockIdx.x * ROWS_PER_BLOCK;
    const float4* __restrict__ gin4 = (const float4*)(in + rowbase * 64);
    float4* __restrict__ gout4 = (float4*)(out + rowbase * 64);

    // ---- coalesced cooperative load (16B/lane) ----
    #pragma unroll
    for (int i = tid; i < ROWS_PER_BLOCK * 32; i += THREADS) {
        float4 v = gin4[i];
        int row = i >> 5;
        int col = (i & 31) << 1;
        sm[row*PAD + col    ] = make_float2(v.x, v.y);
        sm[row*PAD + col + 1] = make_float2(v.z, v.w);
    }
    __syncthreads();

    const int r = tid >> 3;   // row within block
    const int l = tid & 7;    // lane within FFT (= n2, later = k1)
    float2* srow = sm + r * PAD;

    // ---- inner FFT8 over n1 : thread reads x[l + 8*j] ----
    float2 v[8];
    #pragma unroll
    for (int j = 0; j < 8; j++) v[j] = srow[8*j + l];
    fft8(v);

    // ---- twiddle W64^{l * k1} ----
    const float base = -6.28318530717958647692f * (1.0f/64.0f) * (float)l;
    #pragma unroll
    for (int k1 = 1; k1 < 8; k1++) {
        float s, c;
        __sincosf(base * (float)k1, &s, &c);
        v[k1] = cmul(v[k1], make_float2(c, s));
    }
    // write transposed: position k1*8 + n2  (thread owns column-set {8m+l}, no
    // cross-thread hazard with its own reads above)
    #pragma unroll
    for (int k1 = 0; k1 < 8; k1++) srow[k1*8 + l] = v[k1];
    __syncthreads();

    // ---- outer FFT8 over n2 : thread owns k1 = l, reads contiguous 8 ----
    #pragma unroll
    for (int n2 = 0; n2 < 8; n2++) v[n2] = srow[l*8 + n2];
    __syncthreads();   // all reads done before anyone overwrites
    fft8(v);

    // ---- write with fftshift: X[k1 + 8*k2] -> index ((k+32)&63) = l + 8*((k2+4)&7) ----
    #pragma unroll
    for (int k2 = 0; k2 < 8; k2++) {
        int kk = (k2 + 4) & 7;
        srow[kk*8 + l] = v[k2];
    }
    __syncthreads();

    // ---- coalesced cooperative store (16B/lane) ----
    #pragma unroll
    for (int i = tid; i < ROWS_PER_BLOCK * 32; i += THREADS) {
        int row = i >> 5;
        int col = (i & 31) << 1;
        float2 a = sm[row*PAD + col];
        float2 b = sm[row*PAD + col + 1];
        gout4[i] = make_float4(a.x, a.y, b.x, b.y);
    }
}

extern "C" void kernel_launch(void* const* d_in, const int* in_sizes, int n_in,
                              void* d_out, int out_size) {
    const float2* in = (const float2*)d_in[0];
    float2* out = (float2*)d_out;
    // each row = 64 complex = 128 floats
    int nrows  = in_sizes[0] / 128;               // 4096*64 = 262144
    int blocks = nrows / ROWS_PER_BLOCK;          // 8192
    fft64_kernel<<<blocks, THREADS>>>(in, out);
}

// round 2
// speedup vs baseline: 1.5162x; 1.5162x over previous
#include <cuda_runtime.h>

#define THREADS        256
#define ROWS_PER_BLOCK 32     // 8 threads per 64-pt FFT
#define PADT           72     // float2 row stride; 72 % 16 == 8 -> conflict-free phases

__device__ __forceinline__ float2 cadd(float2 a, float2 b){ return make_float2(a.x+b.x, a.y+b.y); }
__device__ __forceinline__ float2 csub(float2 a, float2 b){ return make_float2(a.x-b.x, a.y-b.y); }
__device__ __forceinline__ float2 cmul(float2 a, float2 b){
    return make_float2(fmaf(a.x, b.x, -a.y*b.y), fmaf(a.x, b.y, a.y*b.x));
}
// multiply by -i
__device__ __forceinline__ float2 mul_mi(float2 a){ return make_float2(a.y, -a.x); }

// 8-point FFT, natural-order in/out (DIF + bit-reversal fixup). Forward (e^{-i...}).
__device__ __forceinline__ void fft8(float2 v[8]) {
    const float C = 0.70710678118654752440f;
    float2 a0=v[0],a1=v[1],a2=v[2],a3=v[3],a4=v[4],a5=v[5],a6=v[6],a7=v[7];
    float2 b0=cadd(a0,a4), b4=csub(a0,a4);
    float2 b1=cadd(a1,a5), t5=csub(a1,a5);
    float2 b2=cadd(a2,a6), t6=csub(a2,a6);
    float2 b3=cadd(a3,a7), t7=csub(a3,a7);
    float2 b5 = make_float2(C*(t5.x+t5.y), C*(t5.y-t5.x));   // * W8^1
    float2 b6 = mul_mi(t6);                                   // * W8^2
    float2 b7 = make_float2(C*(t7.y-t7.x), -C*(t7.x+t7.y));  // * W8^3
    float2 c0=cadd(b0,b2), c2=csub(b0,b2);
    float2 c1=cadd(b1,b3), c3=mul_mi(csub(b1,b3));
    float2 c4=cadd(b4,b6), c6=csub(b4,b6);
    float2 c5=cadd(b5,b7), c7=mul_mi(csub(b5,b7));
    float2 d0=cadd(c0,c1), d1=csub(c0,c1);
    float2 d2=cadd(c2,c3), d3=csub(c2,c3);
    float2 d4=cadd(c4,c5), d5=csub(c4,c5);
    float2 d6=cadd(c6,c7), d7=csub(c6,c7);
    v[0]=d0; v[4]=d1; v[2]=d2; v[6]=d3; v[1]=d4; v[5]=d5; v[3]=d6; v[7]=d7;
}

// One 64-pt FFT per 8-thread group; 4 groups per warp; warp-local transpose.
// x[n], n = n2 + 8*n1 (thread owns n2 = l); inner FFT8 over n1 -> Y_l[k1],
// twiddle W64^{l*k1}, smem transpose within warp, outer FFT8 over n2 -> X[l+8k2],
// fftshift folded into the global store index.
__global__ void __launch_bounds__(THREADS)
fft64_kernel(const float2* __restrict__ in, float2* __restrict__ out) {
    __shared__ float2 sm[ROWS_PER_BLOCK * PADT];
    const int tid = threadIdx.x;
    const int r   = tid >> 3;      // row within block
    const int l   = tid & 7;       // lane within FFT group
    const long long row = (long long)blockIdx.x * ROWS_PER_BLOCK + r;
    const float2* __restrict__ gr = in  + row * 64;
    float2*       __restrict__ go = out + row * 64;

    // ---- direct strided loads: 8 x LDG.64, fully coalesced per warp ----
    float2 v[8];
    #pragma unroll
    for (int j = 0; j < 8; j++) v[j] = gr[8*j + l];

    // ---- inner FFT8 over n1 ----
    fft8(v);

    // ---- twiddle W64^{l*k1}: one sincos + power recurrence ----
    {
        float s0, c0;
        __sincosf(-6.28318530717958647692f * (1.0f/64.0f) * (float)l, &s0, &c0);
        float2 w  = make_float2(c0, s0);
        float2 wk = w;
        #pragma unroll
        for (int k1 = 1; k1 < 8; k1++) {
            v[k1] = cmul(v[k1], wk);
            wk = cmul(wk, w);
        }
    }

    // ---- warp-local 8x8 transpose via smem (xor-swizzled, conflict-free) ----
    float2* srow = sm + r * PADT;
    #pragma unroll
    for (int k1 = 0; k1 < 8; k1++) srow[k1*8 + (l ^ k1)] = v[k1];
    __syncwarp();
    #pragma unroll
    for (int n2 = 0; n2 < 8; n2++) v[n2] = srow[l*8 + (n2 ^ l)];

    // ---- outer FFT8 over n2 ----
    fft8(v);

    // ---- direct strided stores with fftshift: k = l + 8*k2 -> l + 8*((k2+4)&7) ----
    #pragma unroll
    for (int k2 = 0; k2 < 8; k2++) {
        go[(((k2 + 4) & 7) << 3) + l] = v[k2];
    }
}

extern "C" void kernel_launch(void* const* d_in, const int* in_sizes, int n_in,
                              void* d_out, int out_size) {
    const float2* in = (const float2*)d_in[0];
    float2* out = (float2*)d_out;
    int nrows  = in_sizes[0] / 128;        // 262144 rows of 64 complex
    int blocks = nrows / ROWS_PER_BLOCK;   // 8192
    fft64_kernel<<<blocks, THREADS>>>(in, out);
}

// round 3
// speedup vs baseline: 1.5173x; 1.0007x over previous
#include <cuda_runtime.h>

#define THREADS        256
#define ROWS_PER_BLOCK 64    // 4 threads per 64-pt FFT

__device__ __forceinline__ float2 cadd(float2 a, float2 b){ return make_float2(a.x+b.x, a.y+b.y); }
__device__ __forceinline__ float2 csub(float2 a, float2 b){ return make_float2(a.x-b.x, a.y-b.y); }
__device__ __forceinline__ float2 cmul(float2 a, float2 b){
    return make_float2(fmaf(a.x, b.x, -a.y*b.y), fmaf(a.x, b.y, a.y*b.x));
}
__device__ __forceinline__ float2 mul_mi(float2 a){ return make_float2(a.y, -a.x); }

// 8-point FFT, natural-order in/out (DIF + bit-reversal fixup). Forward.
__device__ __forceinline__ void fft8(float2 v[8]) {
    const float C = 0.70710678118654752440f;
    float2 a0=v[0],a1=v[1],a2=v[2],a3=v[3],a4=v[4],a5=v[5],a6=v[6],a7=v[7];
    float2 b0=cadd(a0,a4), b4=csub(a0,a4);
    float2 b1=cadd(a1,a5), t5=csub(a1,a5);
    float2 b2=cadd(a2,a6), t6=csub(a2,a6);
    float2 b3=cadd(a3,a7), t7=csub(a3,a7);
    float2 b5 = make_float2(C*(t5.x+t5.y), C*(t5.y-t5.x));
    float2 b6 = mul_mi(t6);
    float2 b7 = make_float2(C*(t7.y-t7.x), -C*(t7.x+t7.y));
    float2 c0=cadd(b0,b2), c2=csub(b0,b2);
    float2 c1=cadd(b1,b3), c3=mul_mi(csub(b1,b3));
    float2 c4=cadd(b4,b6), c6=csub(b4,b6);
    float2 c5=cadd(b5,b7), c7=mul_mi(csub(b5,b7));
    float2 d0=cadd(c0,c1), d1=csub(c0,c1);
    float2 d2=cadd(c2,c3), d3=csub(c2,c3);
    float2 d4=cadd(c4,c5), d5=csub(c4,c5);
    float2 d6=cadd(c6,c7), d7=csub(c6,c7);
    v[0]=d0; v[4]=d1; v[2]=d2; v[6]=d3; v[1]=d4; v[5]=d5; v[3]=d6; v[7]=d7;
}

// 4 threads per 64-pt FFT. Thread l owns n2 in {2l, 2l+1} (one float4 per load).
// Inner FFT8 over n1 for both n2; twiddle W64^{n2*k1}; 128-bit conflict-free
// smem transpose; outer FFT8 over n2 at k1 in {2l, 2l+1}; fftshift folded into
// the 128-bit global store index.
__global__ void __launch_bounds__(THREADS, 4)
fft64_kernel(const float4* __restrict__ in, float4* __restrict__ out) {
    __shared__ float4 sm[ROWS_PER_BLOCK * 32];
    const int tid = threadIdx.x;
    const int l   = tid & 3;      // lane within FFT group
    const int r   = tid >> 2;     // row within block
    const long long row = (long long)blockIdx.x * ROWS_PER_BLOCK + r;
    const float4* __restrict__ gr = in  + row * 32;
    float4*       __restrict__ go = out + row * 32;

    // ---- loads: 8 x LDG.128 (elements 8j+2l, 8j+2l+1) ----
    float2 va[8], vb[8];
    #pragma unroll
    for (int j = 0; j < 8; j++) {
        float4 t = __ldcs(gr + j*4 + l);
        va[j] = make_float2(t.x, t.y);
        vb[j] = make_float2(t.z, t.w);
    }

    // ---- inner FFT8 over n1 for n2=2l and n2=2l+1 ----
    fft8(va);
    fft8(vb);

    // ---- twiddles W64^{n2*k1} via sincos + power recurrence ----
    {
        const float K = -6.28318530717958647692f * (1.0f/64.0f);
        float s, c;
        __sincosf(K * (float)(2*l), &s, &c);
        float2 wa = make_float2(c, s), wka = wa;
        __sincosf(K * (float)(2*l + 1), &s, &c);
        float2 wb = make_float2(c, s), wkb = wb;
        #pragma unroll
        for (int k1 = 1; k1 < 8; k1++) {
            va[k1] = cmul(va[k1], wka);  wka = cmul(wka, wa);
            vb[k1] = cmul(vb[k1], wkb);  wkb = cmul(wkb, wb);
        }
    }

    // ---- 128-bit smem transpose, conflict-free swizzle ----
    // logical (k1, p): float4 = (Y'[2p][k1], Y'[2p+1][k1]) at col (p + (k1>>1))&3,
    // plus row-parity xor of 4 float4 (16 words) to stagger consecutive rows.
    float4* srow = sm + r * 32;
    const int rx = (r & 1) << 2;
    #pragma unroll
    for (int k1 = 0; k1 < 8; k1++) {
        int f = k1*4 + ((l + (k1 >> 1)) & 3);
        srow[f ^ rx] = make_float4(va[k1].x, va[k1].y, vb[k1].x, vb[k1].y);
    }
    __syncwarp();

    // ---- gather k1 = 2l and 2l+1 across all n2 ----
    float2 ua[8], ub[8];
    #pragma unroll
    for (int m = 0; m < 4; m++) {
        int c0 = (m + l) & 3;
        float4 t0 = srow[((2*l    )*4 + c0) ^ rx];  // k1 = 2l
        float4 t1 = srow[((2*l + 1)*4 + c0) ^ rx];  // k1 = 2l+1
        ua[2*m] = make_float2(t0.x, t0.y);  ua[2*m+1] = make_float2(t0.z, t0.w);
        ub[2*m] = make_float2(t1.x, t1.y);  ub[2*m+1] = make_float2(t1.z, t1.w);
    }

    // ---- outer FFT8 over n2 ----
    fft8(ua);
    fft8(ub);

    // ---- stores: 8 x STG.128 with fftshift: k=k1+8k2 -> k1 + 8*((k2+4)&7) ----
    #pragma unroll
    for (int k2 = 0; k2 < 8; k2++) {
        int kk = (k2 + 4) & 7;
        __stcs(go + kk*4 + l,
               make_float4(ua[k2].x, ua[k2].y, ub[k2].x, ub[k2].y));
    }
}

extern "C" void kernel_launch(void* const* d_in, const int* in_sizes, int n_in,
                              void* d_out, int out_size) {
    const float4* in = (const float4*)d_in[0];
    float4* out = (float4*)d_out;
    int nrows  = in_sizes[0] / 128;         // 262144 rows of 64 complex
    int blocks = nrows / ROWS_PER_BLOCK;    // 4096
    fft64_kernel<<<blocks, THREADS>>>(in, out);
}